// round 2
// baseline (speedup 1.0000x reference)
#include <cuda_runtime.h>
#include <cstdint>

#define S_LEN   2048
#define DMODEL  1024
#define BATCH   2
#define NHEADS  16
#define HDIM    64
#define QKV_LD  3072
#define NS_MAX  8

// Scratch (no cudaMalloc allowed): qkv interleaved [B*S, 3D], ctx [B*S, D]
__device__ float g_qkv[(size_t)BATCH * S_LEN * QKV_LD];
__device__ float g_ctx[(size_t)BATCH * S_LEN * DMODEL];

// ---------------------------------------------------------------------------
// Generic tiled GEMM: C[M,N] = A[M,K] @ B[K,N] + bias[N]
// BM=BN=128, BK=16, 256 threads, 8x8 microtile. All dims multiples of tiles.
// ---------------------------------------------------------------------------
__global__ void __launch_bounds__(256) gemm_bias_kernel(
    const float* __restrict__ A, const float* __restrict__ B,
    const float* __restrict__ bias, float* __restrict__ C,
    int M, int N, int K)
{
    __shared__ float As[16][128];
    __shared__ float Bs[16][128];

    const int tid  = threadIdx.x;
    const int bm   = blockIdx.y * 128;
    const int bn   = blockIdx.x * 128;
    const int arow = tid >> 2;          // 0..63 (rows arow, arow+64)
    const int ak4  = (tid & 3) * 4;     // k offset within tile
    const int brow = tid >> 5;          // 0..7 (rows brow, brow+8)
    const int bn4  = (tid & 31) * 4;    // n offset within tile
    const int ty   = tid >> 4;          // 0..15
    const int tx   = tid & 15;          // 0..15

    float acc[8][8];
#pragma unroll
    for (int i = 0; i < 8; i++)
#pragma unroll
        for (int j = 0; j < 8; j++) acc[i][j] = 0.f;

    for (int k0 = 0; k0 < K; k0 += 16) {
        float4 a0 = *(const float4*)&A[(size_t)(bm + arow)      * K + k0 + ak4];
        float4 a1 = *(const float4*)&A[(size_t)(bm + arow + 64) * K + k0 + ak4];
        float4 b0 = *(const float4*)&B[(size_t)(k0 + brow)     * N + bn + bn4];
        float4 b1 = *(const float4*)&B[(size_t)(k0 + brow + 8) * N + bn + bn4];

        __syncthreads();   // previous iteration's smem reads done
        As[ak4 + 0][arow] = a0.x;  As[ak4 + 1][arow] = a0.y;
        As[ak4 + 2][arow] = a0.z;  As[ak4 + 3][arow] = a0.w;
        As[ak4 + 0][arow + 64] = a1.x;  As[ak4 + 1][arow + 64] = a1.y;
        As[ak4 + 2][arow + 64] = a1.z;  As[ak4 + 3][arow + 64] = a1.w;
        *(float4*)&Bs[brow][bn4]     = b0;
        *(float4*)&Bs[brow + 8][bn4] = b1;
        __syncthreads();

#pragma unroll
        for (int kk = 0; kk < 16; kk++) {
            float ra[8], rb[8];
            *(float4*)&ra[0] = *(float4*)&As[kk][ty * 8];
            *(float4*)&ra[4] = *(float4*)&As[kk][ty * 8 + 4];
            *(float4*)&rb[0] = *(float4*)&Bs[kk][tx * 8];
            *(float4*)&rb[4] = *(float4*)&Bs[kk][tx * 8 + 4];
#pragma unroll
            for (int i = 0; i < 8; i++)
#pragma unroll
                for (int j = 0; j < 8; j++)
                    acc[i][j] += ra[i] * rb[j];
        }
    }

#pragma unroll
    for (int i = 0; i < 8; i++) {
        const int row = bm + ty * 8 + i;
#pragma unroll
        for (int j = 0; j < 8; j += 4) {
            const int col = bn + tx * 8 + j;
            float4 o;
            o.x = acc[i][j + 0] + bias[col + 0];
            o.y = acc[i][j + 1] + bias[col + 1];
            o.z = acc[i][j + 2] + bias[col + 2];
            o.w = acc[i][j + 3] + bias[col + 3];
            *(float4*)&C[(size_t)row * N + col] = o;
        }
    }
}

// ---------------------------------------------------------------------------
// Per-position "ns" overwrite: for n < n_eff, row pos+n of q/k/v gets
// tokens[b, pos+n, :] @ W{q,k,v}_ns[n] + b{q,k,v}_ns[n].
// grid = 48 (3 mats x 2 batch x 8 n), 256 threads, each thread 4 outputs.
// ---------------------------------------------------------------------------
__global__ void __launch_bounds__(256) ns_kernel(
    const float* __restrict__ tokens, const int* __restrict__ seqc,
    const float* __restrict__ Wq, const float* __restrict__ bq,
    const float* __restrict__ Wk, const float* __restrict__ bk,
    const float* __restrict__ Wv, const float* __restrict__ bv)
{
    __shared__ float st[DMODEL];
    const int bxid = blockIdx.x;
    const int mat = bxid >> 4;          // 0=q,1=k,2=v
    const int b   = (bxid >> 3) & 1;
    const int n   = bxid & 7;

    const int pos = *seqc;
    const int row = pos + n;
    if (pos < 0 || row < 0 || row >= S_LEN) return;   // n >= n_eff

    const float* W; const float* bb;
    if (mat == 0)      { W = Wq; bb = bq; }
    else if (mat == 1) { W = Wk; bb = bk; }
    else               { W = Wv; bb = bv; }
    W  += (size_t)n * DMODEL * DMODEL;
    bb += n * DMODEL;

    const float* trow = tokens + ((size_t)b * S_LEN + row) * DMODEL;
    const int tid = threadIdx.x;
    *(float4*)&st[tid * 4] = *(const float4*)&trow[tid * 4];
    __syncthreads();

    float acc[4];
#pragma unroll
    for (int j = 0; j < 4; j++) acc[j] = bb[tid + 256 * j];

    for (int d = 0; d < DMODEL; d++) {
        const float td = st[d];
        const float* wr = W + (size_t)d * DMODEL;
#pragma unroll
        for (int j = 0; j < 4; j++) acc[j] += td * wr[tid + 256 * j];
    }

    float* out = g_qkv + ((size_t)b * S_LEN + row) * QKV_LD + mat * DMODEL;
#pragma unroll
    for (int j = 0; j < 4; j++) out[tid + 256 * j] = acc[j];
}

// ---------------------------------------------------------------------------
// Flash attention, fp32, causal + padding mask.
// Block: 8 warps x 8 query rows = 64 rows. Key tiles of 32 (lane = key).
// Lane owns output dims d=lane and d=lane+32.
// Mask is read as 4-byte elements (int32 `1` or float32 `1.0f` both != 0).
// ---------------------------------------------------------------------------
__global__ void __launch_bounds__(256) attn_kernel(
    const unsigned int* __restrict__ mask)
{
    __shared__ float sQ[64][64];
    __shared__ float sKt[64][33];     // [d][key], pad 33 -> conflict-free
    __shared__ float sV[32][64];      // [key][d]
    __shared__ float sP[8][8][32];    // [warp][row][key]

    const int tid  = threadIdx.x;
    const int w    = tid >> 5;
    const int lane = tid & 31;
    const int bx   = blockIdx.x;
    const int b    = blockIdx.y >> 4;
    const int h    = blockIdx.y & 15;
    const int r0   = bx * 64;

    const float* qb = g_qkv + ((size_t)b * S_LEN) * QKV_LD + h * HDIM;
    const float* kb = qb + DMODEL;
    const float* vb = qb + 2 * DMODEL;
    const unsigned int* mb = mask + b * S_LEN;

    {   // load Q tile (64 rows x 64 dims)
        const int row = tid >> 2;
        const int d0  = (tid & 3) * 16;
#pragma unroll
        for (int i = 0; i < 4; i++) {
            const int d = d0 + i * 4;
            *(float4*)&sQ[row][d] =
                *(const float4*)&qb[(size_t)(r0 + row) * QKV_LD + d];
        }
    }

    float m_i[8], l_i[8], a0[8], a1[8];
#pragma unroll
    for (int r = 0; r < 8; r++) { m_i[r] = -1e30f; l_i[r] = 0.f; a0[r] = 0.f; a1[r] = 0.f; }

    const int ntiles = (r0 + 64) >> 5;
    const int kkey = tid >> 3;   // 0..31
    const int kc   = tid & 7;

    for (int t = 0; t < ntiles; t++) {
        const int k0 = t << 5;
        __syncthreads();   // previous tile fully consumed
#pragma unroll
        for (int i = 0; i < 2; i++) {
            const int d = (kc + i * 8) * 4;
            float4 kv = *(const float4*)&kb[(size_t)(k0 + kkey) * QKV_LD + d];
            sKt[d + 0][kkey] = kv.x;  sKt[d + 1][kkey] = kv.y;
            sKt[d + 2][kkey] = kv.z;  sKt[d + 3][kkey] = kv.w;
            float4 vv = *(const float4*)&vb[(size_t)(k0 + kkey) * QKV_LD + d];
            *(float4*)&sV[kkey][d] = vv;
        }
        __syncthreads();

        // scores: s[r] = q_row . k_lane
        float s[8];
#pragma unroll
        for (int r = 0; r < 8; r++) s[r] = 0.f;
#pragma unroll
        for (int d4 = 0; d4 < 16; d4++) {
            const float k0v = sKt[d4 * 4 + 0][lane];
            const float k1v = sKt[d4 * 4 + 1][lane];
            const float k2v = sKt[d4 * 4 + 2][lane];
            const float k3v = sKt[d4 * 4 + 3][lane];
#pragma unroll
            for (int r = 0; r < 8; r++) {
                float4 qq = *(float4*)&sQ[w * 8 + r][d4 * 4];
                s[r] += qq.x * k0v + qq.y * k1v + qq.z * k2v + qq.w * k3v;
            }
        }

        const int keyg = k0 + lane;
        const bool mval = (mb[keyg] != 0u);
#pragma unroll
        for (int r = 0; r < 8; r++) {
            const int rg = r0 + w * 8 + r;
            s[r] = (mval && keyg <= rg) ? s[r] * 0.125f : -1e9f;
        }

        // online softmax per row
#pragma unroll
        for (int r = 0; r < 8; r++) {
            float tm = s[r];
#pragma unroll
            for (int off = 16; off > 0; off >>= 1)
                tm = fmaxf(tm, __shfl_xor_sync(0xffffffffu, tm, off));
            const float mnew = fmaxf(m_i[r], tm);
            const float p    = __expf(s[r] - mnew);
            const float corr = __expf(m_i[r] - mnew);
            float ps = p;
#pragma unroll
            for (int off = 16; off > 0; off >>= 1)
                ps += __shfl_xor_sync(0xffffffffu, ps, off);
            l_i[r] = l_i[r] * corr + ps;
            a0[r] *= corr;  a1[r] *= corr;
            m_i[r] = mnew;
            sP[w][r][lane] = p;
        }
        __syncwarp();

        // PV accumulate
#pragma unroll
        for (int j4 = 0; j4 < 8; j4++) {
            const float v00 = sV[j4 * 4 + 0][lane];
            const float v01 = sV[j4 * 4 + 1][lane];
            const float v02 = sV[j4 * 4 + 2][lane];
            const float v03 = sV[j4 * 4 + 3][lane];
            const float v10 = sV[j4 * 4 + 0][lane + 32];
            const float v11 = sV[j4 * 4 + 1][lane + 32];
            const float v12 = sV[j4 * 4 + 2][lane + 32];
            const float v13 = sV[j4 * 4 + 3][lane + 32];
#pragma unroll
            for (int r = 0; r < 8; r++) {
                float4 pp = *(float4*)&sP[w][r][j4 * 4];
                a0[r] += pp.x * v00 + pp.y * v01 + pp.z * v02 + pp.w * v03;
                a1[r] += pp.x * v10 + pp.y * v11 + pp.z * v12 + pp.w * v13;
            }
        }
        __syncwarp();
    }

#pragma unroll
    for (int r = 0; r < 8; r++) {
        const int rg = r0 + w * 8 + r;
        const float inv = 1.f / l_i[r];
        float* o = g_ctx + ((size_t)(b * S_LEN) + rg) * DMODEL + h * HDIM;
        o[lane]      = a0[r] * inv;
        o[lane + 32] = a1[r] * inv;
    }
}

// ---------------------------------------------------------------------------
extern "C" void kernel_launch(void* const* d_in, const int* in_sizes, int n_in,
                              void* d_out, int out_size)
{
    const float*        tokens = (const float*)d_in[0];
    const unsigned int* mask   = (const unsigned int*)d_in[1];
    const int*          seqc   = (const int*)d_in[2];
    const float*        W_qkv  = (const float*)d_in[3];
    const float*        b_qkv  = (const float*)d_in[4];
    const float*        Wq     = (const float*)d_in[5];
    const float*        bq     = (const float*)d_in[6];
    const float*        Wk     = (const float*)d_in[7];
    const float*        bk     = (const float*)d_in[8];
    const float*        Wv     = (const float*)d_in[9];
    const float*        bv     = (const float*)d_in[10];
    const float*        W_out  = (const float*)d_in[11];
    const float*        b_out  = (const float*)d_in[12];
    float*              out    = (float*)d_out;

    float* qkv = nullptr;
    float* ctx = nullptr;
    cudaGetSymbolAddress((void**)&qkv, g_qkv);
    cudaGetSymbolAddress((void**)&ctx, g_ctx);

    const int M = BATCH * S_LEN;   // 4096

    // 1) fused QKV projection: [4096,1024] @ [1024,3072] + bias
    dim3 g1(QKV_LD / 128, M / 128);
    gemm_bias_kernel<<<g1, 256>>>(tokens, W_qkv, b_qkv, qkv, M, QKV_LD, DMODEL);

    // 2) per-position ns overwrites (reads seq_token_count on device)
    ns_kernel<<<48, 256>>>(tokens, seqc, Wq, bq, Wk, bk, Wv, bv);

    // 3) causal flash attention -> g_ctx
    dim3 g2(S_LEN / 64, BATCH * NHEADS);
    attn_kernel<<<g2, 256>>>(mask);

    // 4) output projection: [4096,1024] @ [1024,1024] + bias -> d_out
    dim3 g3(DMODEL / 128, M / 128);
    gemm_bias_kernel<<<g3, 256>>>(ctx, W_out, b_out, out, M, DMODEL, DMODEL);
}

// round 3
// speedup vs baseline: 1.2656x; 1.2656x over previous
#include <cuda_runtime.h>
#include <cuda_bf16.h>
#include <cstdint>

#define S_LEN   2048
#define DMODEL  1024
#define BATCH   2
#define NHEADS  16
#define HDIM    64
#define QKV_LD  3072

// Scratch: qkv interleaved [B*S, 3D], ctx [B*S, D]
__device__ float g_qkv[(size_t)BATCH * S_LEN * QKV_LD];
__device__ float g_ctx[(size_t)BATCH * S_LEN * DMODEL];

// ---------------------------------------------------------------------------
// bf16x3 compensated tensor-core GEMM: C[M,N] = A[M,K] @ B[K,N] + bias[N]
// fp32 in/out. Each fp32 split into bf16 hi + bf16 lo; D accumulates
// Ahi*Bhi + Ahi*Blo + Alo*Bhi in fp32 (lo*lo dropped, ~2^-18 rel/term).
// BM=BN=128, BK=32, 256 threads (8 warps), warp tile 64x32 via m16n8k16.
// ---------------------------------------------------------------------------
__device__ __forceinline__ void mma_bf16(float* d, const uint32_t* a, const uint32_t* b) {
    asm volatile(
        "mma.sync.aligned.m16n8k16.row.col.f32.bf16.bf16.f32 "
        "{%0,%1,%2,%3}, {%4,%5,%6,%7}, {%8,%9}, {%0,%1,%2,%3};\n"
        : "+f"(d[0]), "+f"(d[1]), "+f"(d[2]), "+f"(d[3])
        : "r"(a[0]), "r"(a[1]), "r"(a[2]), "r"(a[3]), "r"(b[0]), "r"(b[1]));
}

__device__ __forceinline__ void split2(float x, __nv_bfloat16& hi, __nv_bfloat16& lo) {
    hi = __float2bfloat16(x);
    lo = __float2bfloat16(x - __bfloat162float(hi));
}

__global__ void __launch_bounds__(256) gemm_bf16x3_kernel(
    const float* __restrict__ A, const float* __restrict__ B,
    const float* __restrict__ bias, float* __restrict__ C,
    int M, int N, int K)
{
    __shared__ __nv_bfloat16 sAhi[128][40];   // [m][k], pad 8 -> frag-load conflict-free
    __shared__ __nv_bfloat16 sAlo[128][40];
    __shared__ __nv_bfloat16 sBhi[32][136];   // [k][n], pad 8
    __shared__ __nv_bfloat16 sBlo[32][136];

    const int tid    = threadIdx.x;
    const int lane   = tid & 31;
    const int wid    = tid >> 5;
    const int bm     = blockIdx.y * 128;
    const int bn     = blockIdx.x * 128;
    const int warp_m = (wid >> 2) * 64;       // 0 or 64
    const int warp_n = (wid & 3) * 32;        // 0..96

    float acc[4][4][4];
#pragma unroll
    for (int mi = 0; mi < 4; mi++)
#pragma unroll
        for (int ni = 0; ni < 4; ni++)
#pragma unroll
            for (int r = 0; r < 4; r++) acc[mi][ni][r] = 0.f;

    float4 av[4], bv[4];
    // prefetch first tile
#pragma unroll
    for (int i = 0; i < 4; i++) {
        const int f = tid + i * 256;
        av[i] = *(const float4*)&A[(size_t)(bm + (f >> 3)) * K + (f & 7) * 4];
        bv[i] = *(const float4*)&B[(size_t)(f >> 5) * N + bn + (f & 31) * 4];
    }

    for (int k0 = 0; k0 < K; k0 += 32) {
        __syncthreads();   // prev compute done reading smem
#pragma unroll
        for (int i = 0; i < 4; i++) {
            const int f    = tid + i * 256;
            const int arow = f >> 3, acol = (f & 7) * 4;
            const int krow = f >> 5, ncol = (f & 31) * 4;
            __nv_bfloat16 h0, l0, h1, l1, h2, l2, h3, l3;
            split2(av[i].x, h0, l0); split2(av[i].y, h1, l1);
            split2(av[i].z, h2, l2); split2(av[i].w, h3, l3);
            sAhi[arow][acol+0] = h0; sAhi[arow][acol+1] = h1;
            sAhi[arow][acol+2] = h2; sAhi[arow][acol+3] = h3;
            sAlo[arow][acol+0] = l0; sAlo[arow][acol+1] = l1;
            sAlo[arow][acol+2] = l2; sAlo[arow][acol+3] = l3;
            split2(bv[i].x, h0, l0); split2(bv[i].y, h1, l1);
            split2(bv[i].z, h2, l2); split2(bv[i].w, h3, l3);
            sBhi[krow][ncol+0] = h0; sBhi[krow][ncol+1] = h1;
            sBhi[krow][ncol+2] = h2; sBhi[krow][ncol+3] = h3;
            sBlo[krow][ncol+0] = l0; sBlo[krow][ncol+1] = l1;
            sBlo[krow][ncol+2] = l2; sBlo[krow][ncol+3] = l3;
        }
        __syncthreads();

        // prefetch next tile while computing this one
        if (k0 + 32 < K) {
            const int kn = k0 + 32;
#pragma unroll
            for (int i = 0; i < 4; i++) {
                const int f = tid + i * 256;
                av[i] = *(const float4*)&A[(size_t)(bm + (f >> 3)) * K + kn + (f & 7) * 4];
                bv[i] = *(const float4*)&B[(size_t)(kn + (f >> 5)) * N + bn + (f & 31) * 4];
            }
        }

#pragma unroll
        for (int ks = 0; ks < 2; ks++) {
            const int kb = ks * 16;
            uint32_t ah[4][4], al[4][4], bh[4][2], bl[4][2];
#pragma unroll
            for (int mi = 0; mi < 4; mi++) {
                const int m = warp_m + mi * 16 + (lane >> 2);
                const int c = kb + (lane & 3) * 2;
                ah[mi][0] = *(const uint32_t*)&sAhi[m][c];
                ah[mi][1] = *(const uint32_t*)&sAhi[m + 8][c];
                ah[mi][2] = *(const uint32_t*)&sAhi[m][c + 8];
                ah[mi][3] = *(const uint32_t*)&sAhi[m + 8][c + 8];
                al[mi][0] = *(const uint32_t*)&sAlo[m][c];
                al[mi][1] = *(const uint32_t*)&sAlo[m + 8][c];
                al[mi][2] = *(const uint32_t*)&sAlo[m][c + 8];
                al[mi][3] = *(const uint32_t*)&sAlo[m + 8][c + 8];
            }
#pragma unroll
            for (int ni = 0; ni < 4; ni++) {
                const int n  = warp_n + ni * 8 + (lane >> 2);
                const int kk = kb + (lane & 3) * 2;
                uint32_t u0, u1;
                u0 = *(const unsigned short*)&sBhi[kk][n];
                u1 = *(const unsigned short*)&sBhi[kk + 1][n];
                bh[ni][0] = u0 | (u1 << 16);
                u0 = *(const unsigned short*)&sBhi[kk + 8][n];
                u1 = *(const unsigned short*)&sBhi[kk + 9][n];
                bh[ni][1] = u0 | (u1 << 16);
                u0 = *(const unsigned short*)&sBlo[kk][n];
                u1 = *(const unsigned short*)&sBlo[kk + 1][n];
                bl[ni][0] = u0 | (u1 << 16);
                u0 = *(const unsigned short*)&sBlo[kk + 8][n];
                u1 = *(const unsigned short*)&sBlo[kk + 9][n];
                bl[ni][1] = u0 | (u1 << 16);
            }
#pragma unroll
            for (int mi = 0; mi < 4; mi++)
#pragma unroll
                for (int ni = 0; ni < 4; ni++) {
                    mma_bf16(acc[mi][ni], ah[mi], bh[ni]);
                    mma_bf16(acc[mi][ni], ah[mi], bl[ni]);
                    mma_bf16(acc[mi][ni], al[mi], bh[ni]);
                }
        }
    }

    // epilogue: D-frag layout -> gmem + bias
#pragma unroll
    for (int mi = 0; mi < 4; mi++) {
        const int row = bm + warp_m + mi * 16 + (lane >> 2);
#pragma unroll
        for (int ni = 0; ni < 4; ni++) {
            const int col = bn + warp_n + ni * 8 + (lane & 3) * 2;
            const float2 bb = *(const float2*)&bias[col];
            float2 o0, o1;
            o0.x = acc[mi][ni][0] + bb.x;  o0.y = acc[mi][ni][1] + bb.y;
            o1.x = acc[mi][ni][2] + bb.x;  o1.y = acc[mi][ni][3] + bb.y;
            *(float2*)&C[(size_t)row * N + col]       = o0;
            *(float2*)&C[(size_t)(row + 8) * N + col] = o1;
        }
    }
}

// ---------------------------------------------------------------------------
// Per-position "ns" overwrite (48 blocks: 3 mats x 2 batch x 8 n)
// ---------------------------------------------------------------------------
__global__ void __launch_bounds__(256) ns_kernel(
    const float* __restrict__ tokens, const int* __restrict__ seqc,
    const float* __restrict__ Wq, const float* __restrict__ bq,
    const float* __restrict__ Wk, const float* __restrict__ bk,
    const float* __restrict__ Wv, const float* __restrict__ bv)
{
    __shared__ float st[DMODEL];
    const int bxid = blockIdx.x;
    const int mat = bxid >> 4;
    const int b   = (bxid >> 3) & 1;
    const int n   = bxid & 7;

    const int pos = *seqc;
    const int row = pos + n;
    if (pos < 0 || row < 0 || row >= S_LEN) return;

    const float* W; const float* bb;
    if (mat == 0)      { W = Wq; bb = bq; }
    else if (mat == 1) { W = Wk; bb = bk; }
    else               { W = Wv; bb = bv; }
    W  += (size_t)n * DMODEL * DMODEL;
    bb += n * DMODEL;

    const float* trow = tokens + ((size_t)b * S_LEN + row) * DMODEL;
    const int tid = threadIdx.x;
    *(float4*)&st[tid * 4] = *(const float4*)&trow[tid * 4];
    __syncthreads();

    float acc[4];
#pragma unroll
    for (int j = 0; j < 4; j++) acc[j] = bb[tid + 256 * j];

    for (int d = 0; d < DMODEL; d++) {
        const float td = st[d];
        const float* wr = W + (size_t)d * DMODEL;
#pragma unroll
        for (int j = 0; j < 4; j++) acc[j] += td * wr[tid + 256 * j];
    }

    float* out = g_qkv + ((size_t)b * S_LEN + row) * QKV_LD + mat * DMODEL;
#pragma unroll
    for (int j = 0; j < 4; j++) out[tid + 256 * j] = acc[j];
}

// ---------------------------------------------------------------------------
// Flash attention, fp32 SIMT, causal + padding mask (mask = 4-byte elements)
// ---------------------------------------------------------------------------
__global__ void __launch_bounds__(256) attn_kernel(
    const unsigned int* __restrict__ mask)
{
    __shared__ float sQ[64][64];
    __shared__ float sKt[64][33];
    __shared__ float sV[32][64];
    __shared__ float sP[8][8][32];

    const int tid  = threadIdx.x;
    const int w    = tid >> 5;
    const int lane = tid & 31;
    const int bx   = blockIdx.x;
    const int b    = blockIdx.y >> 4;
    const int h    = blockIdx.y & 15;
    const int r0   = bx * 64;

    const float* qb = g_qkv + ((size_t)b * S_LEN) * QKV_LD + h * HDIM;
    const float* kb = qb + DMODEL;
    const float* vb = qb + 2 * DMODEL;
    const unsigned int* mb = mask + b * S_LEN;

    {
        const int row = tid >> 2;
        const int d0  = (tid & 3) * 16;
#pragma unroll
        for (int i = 0; i < 4; i++) {
            const int d = d0 + i * 4;
            *(float4*)&sQ[row][d] =
                *(const float4*)&qb[(size_t)(r0 + row) * QKV_LD + d];
        }
    }

    float m_i[8], l_i[8], a0[8], a1[8];
#pragma unroll
    for (int r = 0; r < 8; r++) { m_i[r] = -1e30f; l_i[r] = 0.f; a0[r] = 0.f; a1[r] = 0.f; }

    const int ntiles = (r0 + 64) >> 5;
    const int kkey = tid >> 3;
    const int kc   = tid & 7;

    for (int t = 0; t < ntiles; t++) {
        const int k0 = t << 5;
        __syncthreads();
#pragma unroll
        for (int i = 0; i < 2; i++) {
            const int d = (kc + i * 8) * 4;
            float4 kv = *(const float4*)&kb[(size_t)(k0 + kkey) * QKV_LD + d];
            sKt[d + 0][kkey] = kv.x;  sKt[d + 1][kkey] = kv.y;
            sKt[d + 2][kkey] = kv.z;  sKt[d + 3][kkey] = kv.w;
            float4 vv = *(const float4*)&vb[(size_t)(k0 + kkey) * QKV_LD + d];
            *(float4*)&sV[kkey][d] = vv;
        }
        __syncthreads();

        float s[8];
#pragma unroll
        for (int r = 0; r < 8; r++) s[r] = 0.f;
#pragma unroll
        for (int d4 = 0; d4 < 16; d4++) {
            const float k0v = sKt[d4 * 4 + 0][lane];
            const float k1v = sKt[d4 * 4 + 1][lane];
            const float k2v = sKt[d4 * 4 + 2][lane];
            const float k3v = sKt[d4 * 4 + 3][lane];
#pragma unroll
            for (int r = 0; r < 8; r++) {
                float4 qq = *(float4*)&sQ[w * 8 + r][d4 * 4];
                s[r] += qq.x * k0v + qq.y * k1v + qq.z * k2v + qq.w * k3v;
            }
        }

        const int keyg = k0 + lane;
        const bool mval = (mb[keyg] != 0u);
#pragma unroll
        for (int r = 0; r < 8; r++) {
            const int rg = r0 + w * 8 + r;
            s[r] = (mval && keyg <= rg) ? s[r] * 0.125f : -1e9f;
        }

#pragma unroll
        for (int r = 0; r < 8; r++) {
            float tm = s[r];
#pragma unroll
            for (int off = 16; off > 0; off >>= 1)
                tm = fmaxf(tm, __shfl_xor_sync(0xffffffffu, tm, off));
            const float mnew = fmaxf(m_i[r], tm);
            const float p    = __expf(s[r] - mnew);
            const float corr = __expf(m_i[r] - mnew);
            float ps = p;
#pragma unroll
            for (int off = 16; off > 0; off >>= 1)
                ps += __shfl_xor_sync(0xffffffffu, ps, off);
            l_i[r] = l_i[r] * corr + ps;
            a0[r] *= corr;  a1[r] *= corr;
            m_i[r] = mnew;
            sP[w][r][lane] = p;
        }
        __syncwarp();

#pragma unroll
        for (int j4 = 0; j4 < 8; j4++) {
            const float v00 = sV[j4 * 4 + 0][lane];
            const float v01 = sV[j4 * 4 + 1][lane];
            const float v02 = sV[j4 * 4 + 2][lane];
            const float v03 = sV[j4 * 4 + 3][lane];
            const float v10 = sV[j4 * 4 + 0][lane + 32];
            const float v11 = sV[j4 * 4 + 1][lane + 32];
            const float v12 = sV[j4 * 4 + 2][lane + 32];
            const float v13 = sV[j4 * 4 + 3][lane + 32];
#pragma unroll
            for (int r = 0; r < 8; r++) {
                float4 pp = *(float4*)&sP[w][r][j4 * 4];
                a0[r] += pp.x * v00 + pp.y * v01 + pp.z * v02 + pp.w * v03;
                a1[r] += pp.x * v10 + pp.y * v11 + pp.z * v12 + pp.w * v13;
            }
        }
        __syncwarp();
    }

#pragma unroll
    for (int r = 0; r < 8; r++) {
        const int rg = r0 + w * 8 + r;
        const float inv = 1.f / l_i[r];
        float* o = g_ctx + ((size_t)(b * S_LEN) + rg) * DMODEL + h * HDIM;
        o[lane]      = a0[r] * inv;
        o[lane + 32] = a1[r] * inv;
    }
}

// ---------------------------------------------------------------------------
extern "C" void kernel_launch(void* const* d_in, const int* in_sizes, int n_in,
                              void* d_out, int out_size)
{
    const float*        tokens = (const float*)d_in[0];
    const unsigned int* mask   = (const unsigned int*)d_in[1];
    const int*          seqc   = (const int*)d_in[2];
    const float*        W_qkv  = (const float*)d_in[3];
    const float*        b_qkv  = (const float*)d_in[4];
    const float*        Wq     = (const float*)d_in[5];
    const float*        bq     = (const float*)d_in[6];
    const float*        Wk     = (const float*)d_in[7];
    const float*        bk     = (const float*)d_in[8];
    const float*        Wv     = (const float*)d_in[9];
    const float*        bv     = (const float*)d_in[10];
    const float*        W_out  = (const float*)d_in[11];
    const float*        b_out  = (const float*)d_in[12];
    float*              out    = (float*)d_out;

    float* qkv = nullptr;
    float* ctx = nullptr;
    cudaGetSymbolAddress((void**)&qkv, g_qkv);
    cudaGetSymbolAddress((void**)&ctx, g_ctx);

    const int M = BATCH * S_LEN;   // 4096

    // 1) fused QKV projection (tensor cores, bf16x3)
    dim3 g1(QKV_LD / 128, M / 128);
    gemm_bf16x3_kernel<<<g1, 256>>>(tokens, W_qkv, b_qkv, qkv, M, QKV_LD, DMODEL);

    // 2) per-position ns overwrites
    ns_kernel<<<48, 256>>>(tokens, seqc, Wq, bq, Wk, bk, Wv, bv);

    // 3) causal flash attention -> g_ctx
    dim3 g2(S_LEN / 64, BATCH * NHEADS);
    attn_kernel<<<g2, 256>>>(mask);

    // 4) output projection (tensor cores, bf16x3) -> d_out
    dim3 g3(DMODEL / 128, M / 128);
    gemm_bf16x3_kernel<<<g3, 256>>>(ctx, W_out, b_out, out, M, DMODEL, DMODEL);
}

// round 4
// speedup vs baseline: 1.9069x; 1.5067x over previous
#include <cuda_runtime.h>
#include <cuda_bf16.h>
#include <cstdint>

#define S_LEN   2048
#define DMODEL  1024
#define BATCH   2
#define NHEADS  16
#define HDIM    64
#define QKV_LD  3072

__device__ float g_qkv[(size_t)BATCH * S_LEN * QKV_LD];
__device__ float g_ctx[(size_t)BATCH * S_LEN * DMODEL];

// ---------------------------------------------------------------------------
__device__ __forceinline__ void mma_bf16(float* d, const uint32_t* a, const uint32_t* b) {
    asm volatile(
        "mma.sync.aligned.m16n8k16.row.col.f32.bf16.bf16.f32 "
        "{%0,%1,%2,%3}, {%4,%5,%6,%7}, {%8,%9}, {%0,%1,%2,%3};\n"
        : "+f"(d[0]), "+f"(d[1]), "+f"(d[2]), "+f"(d[3])
        : "r"(a[0]), "r"(a[1]), "r"(a[2]), "r"(a[3]), "r"(b[0]), "r"(b[1]));
}

__device__ __forceinline__ void split2(float x, __nv_bfloat16& hi, __nv_bfloat16& lo) {
    hi = __float2bfloat16(x);
    lo = __float2bfloat16(x - __bfloat162float(hi));
}

__device__ __forceinline__ void split_pack2(float x, float y, uint32_t& hi, uint32_t& lo) {
    __nv_bfloat16 xh, xl, yh, yl;
    split2(x, xh, xl); split2(y, yh, yl);
    __nv_bfloat162 h2 = __nv_bfloat162(xh, yh);
    __nv_bfloat162 l2 = __nv_bfloat162(xl, yl);
    hi = *(uint32_t*)&h2;  lo = *(uint32_t*)&l2;
}

// ---------------------------------------------------------------------------
// bf16x3 compensated tensor-core GEMM (unchanged from R3)
// ---------------------------------------------------------------------------
__global__ void __launch_bounds__(256) gemm_bf16x3_kernel(
    const float* __restrict__ A, const float* __restrict__ B,
    const float* __restrict__ bias, float* __restrict__ C,
    int M, int N, int K)
{
    __shared__ __nv_bfloat16 sAhi[128][40];
    __shared__ __nv_bfloat16 sAlo[128][40];
    __shared__ __nv_bfloat16 sBhi[32][136];
    __shared__ __nv_bfloat16 sBlo[32][136];

    const int tid    = threadIdx.x;
    const int lane   = tid & 31;
    const int wid    = tid >> 5;
    const int bm     = blockIdx.y * 128;
    const int bn     = blockIdx.x * 128;
    const int warp_m = (wid >> 2) * 64;
    const int warp_n = (wid & 3) * 32;

    float acc[4][4][4];
#pragma unroll
    for (int mi = 0; mi < 4; mi++)
#pragma unroll
        for (int ni = 0; ni < 4; ni++)
#pragma unroll
            for (int r = 0; r < 4; r++) acc[mi][ni][r] = 0.f;

    float4 av[4], bv[4];
#pragma unroll
    for (int i = 0; i < 4; i++) {
        const int f = tid + i * 256;
        av[i] = *(const float4*)&A[(size_t)(bm + (f >> 3)) * K + (f & 7) * 4];
        bv[i] = *(const float4*)&B[(size_t)(f >> 5) * N + bn + (f & 31) * 4];
    }

    for (int k0 = 0; k0 < K; k0 += 32) {
        __syncthreads();
#pragma unroll
        for (int i = 0; i < 4; i++) {
            const int f    = tid + i * 256;
            const int arow = f >> 3, acol = (f & 7) * 4;
            const int krow = f >> 5, ncol = (f & 31) * 4;
            __nv_bfloat16 h0, l0, h1, l1, h2, l2, h3, l3;
            split2(av[i].x, h0, l0); split2(av[i].y, h1, l1);
            split2(av[i].z, h2, l2); split2(av[i].w, h3, l3);
            sAhi[arow][acol+0] = h0; sAhi[arow][acol+1] = h1;
            sAhi[arow][acol+2] = h2; sAhi[arow][acol+3] = h3;
            sAlo[arow][acol+0] = l0; sAlo[arow][acol+1] = l1;
            sAlo[arow][acol+2] = l2; sAlo[arow][acol+3] = l3;
            split2(bv[i].x, h0, l0); split2(bv[i].y, h1, l1);
            split2(bv[i].z, h2, l2); split2(bv[i].w, h3, l3);
            sBhi[krow][ncol+0] = h0; sBhi[krow][ncol+1] = h1;
            sBhi[krow][ncol+2] = h2; sBhi[krow][ncol+3] = h3;
            sBlo[krow][ncol+0] = l0; sBlo[krow][ncol+1] = l1;
            sBlo[krow][ncol+2] = l2; sBlo[krow][ncol+3] = l3;
        }
        __syncthreads();

        if (k0 + 32 < K) {
            const int kn = k0 + 32;
#pragma unroll
            for (int i = 0; i < 4; i++) {
                const int f = tid + i * 256;
                av[i] = *(const float4*)&A[(size_t)(bm + (f >> 3)) * K + kn + (f & 7) * 4];
                bv[i] = *(const float4*)&B[(size_t)(kn + (f >> 5)) * N + bn + (f & 31) * 4];
            }
        }

#pragma unroll
        for (int ks = 0; ks < 2; ks++) {
            const int kb = ks * 16;
            uint32_t ah[4][4], al[4][4], bh[4][2], bl[4][2];
#pragma unroll
            for (int mi = 0; mi < 4; mi++) {
                const int m = warp_m + mi * 16 + (lane >> 2);
                const int c = kb + (lane & 3) * 2;
                ah[mi][0] = *(const uint32_t*)&sAhi[m][c];
                ah[mi][1] = *(const uint32_t*)&sAhi[m + 8][c];
                ah[mi][2] = *(const uint32_t*)&sAhi[m][c + 8];
                ah[mi][3] = *(const uint32_t*)&sAhi[m + 8][c + 8];
                al[mi][0] = *(const uint32_t*)&sAlo[m][c];
                al[mi][1] = *(const uint32_t*)&sAlo[m + 8][c];
                al[mi][2] = *(const uint32_t*)&sAlo[m][c + 8];
                al[mi][3] = *(const uint32_t*)&sAlo[m + 8][c + 8];
            }
#pragma unroll
            for (int ni = 0; ni < 4; ni++) {
                const int n  = warp_n + ni * 8 + (lane >> 2);
                const int kk = kb + (lane & 3) * 2;
                uint32_t u0, u1;
                u0 = *(const unsigned short*)&sBhi[kk][n];
                u1 = *(const unsigned short*)&sBhi[kk + 1][n];
                bh[ni][0] = u0 | (u1 << 16);
                u0 = *(const unsigned short*)&sBhi[kk + 8][n];
                u1 = *(const unsigned short*)&sBhi[kk + 9][n];
                bh[ni][1] = u0 | (u1 << 16);
                u0 = *(const unsigned short*)&sBlo[kk][n];
                u1 = *(const unsigned short*)&sBlo[kk + 1][n];
                bl[ni][0] = u0 | (u1 << 16);
                u0 = *(const unsigned short*)&sBlo[kk + 8][n];
                u1 = *(const unsigned short*)&sBlo[kk + 9][n];
                bl[ni][1] = u0 | (u1 << 16);
            }
#pragma unroll
            for (int mi = 0; mi < 4; mi++)
#pragma unroll
                for (int ni = 0; ni < 4; ni++) {
                    mma_bf16(acc[mi][ni], ah[mi], bh[ni]);
                    mma_bf16(acc[mi][ni], ah[mi], bl[ni]);
                    mma_bf16(acc[mi][ni], al[mi], bh[ni]);
                }
        }
    }

#pragma unroll
    for (int mi = 0; mi < 4; mi++) {
        const int row = bm + warp_m + mi * 16 + (lane >> 2);
#pragma unroll
        for (int ni = 0; ni < 4; ni++) {
            const int col = bn + warp_n + ni * 8 + (lane & 3) * 2;
            const float2 bb = *(const float2*)&bias[col];
            float2 o0, o1;
            o0.x = acc[mi][ni][0] + bb.x;  o0.y = acc[mi][ni][1] + bb.y;
            o1.x = acc[mi][ni][2] + bb.x;  o1.y = acc[mi][ni][3] + bb.y;
            *(float2*)&C[(size_t)row * N + col]       = o0;
            *(float2*)&C[(size_t)(row + 8) * N + col] = o1;
        }
    }
}

// ---------------------------------------------------------------------------
// ns overwrite (unchanged)
// ---------------------------------------------------------------------------
__global__ void __launch_bounds__(256) ns_kernel(
    const float* __restrict__ tokens, const int* __restrict__ seqc,
    const float* __restrict__ Wq, const float* __restrict__ bq,
    const float* __restrict__ Wk, const float* __restrict__ bk,
    const float* __restrict__ Wv, const float* __restrict__ bv)
{
    __shared__ float st[DMODEL];
    const int bxid = blockIdx.x;
    const int mat = bxid >> 4;
    const int b   = (bxid >> 3) & 1;
    const int n   = bxid & 7;

    const int pos = *seqc;
    const int row = pos + n;
    if (pos < 0 || row < 0 || row >= S_LEN) return;

    const float* W; const float* bb;
    if (mat == 0)      { W = Wq; bb = bq; }
    else if (mat == 1) { W = Wk; bb = bk; }
    else               { W = Wv; bb = bv; }
    W  += (size_t)n * DMODEL * DMODEL;
    bb += n * DMODEL;

    const float* trow = tokens + ((size_t)b * S_LEN + row) * DMODEL;
    const int tid = threadIdx.x;
    *(float4*)&st[tid * 4] = *(const float4*)&trow[tid * 4];
    __syncthreads();

    float acc[4];
#pragma unroll
    for (int j = 0; j < 4; j++) acc[j] = bb[tid + 256 * j];

    for (int d = 0; d < DMODEL; d++) {
        const float td = st[d];
        const float* wr = W + (size_t)d * DMODEL;
#pragma unroll
        for (int j = 0; j < 4; j++) acc[j] += td * wr[tid + 256 * j];
    }

    float* out = g_qkv + ((size_t)b * S_LEN + row) * QKV_LD + mat * DMODEL;
#pragma unroll
    for (int j = 0; j < 4; j++) out[tid + 256 * j] = acc[j];
}

// ---------------------------------------------------------------------------
// Tensor-core flash attention, bf16x3 compensated (QK^T and PV).
// Block: 128 q rows, 8 warps (16 rows each). Key tiles of 64. Q in registers.
// ---------------------------------------------------------------------------
__global__ void __launch_bounds__(256) attn_tc_kernel(
    const unsigned int* __restrict__ mask)
{
    __shared__ __nv_bfloat16 sKhi[64][72];   // [key][d]
    __shared__ __nv_bfloat16 sKlo[64][72];
    __shared__ __nv_bfloat16 sVhi[64][72];   // [d][key]  (transposed)
    __shared__ __nv_bfloat16 sVlo[64][72];
    __shared__ unsigned int  sMask[64];

    const int tid  = threadIdx.x;
    const int w    = tid >> 5;
    const int lane = tid & 31;
    const int bx   = blockIdx.x;
    const int b    = blockIdx.y >> 4;
    const int h    = blockIdx.y & 15;
    const int r0   = bx * 128;

    const float* qb = g_qkv + ((size_t)b * S_LEN) * QKV_LD + h * HDIM;
    const float* kb = qb + DMODEL;
    const float* vb = qb + 2 * DMODEL;
    const unsigned int* mb = mask + b * S_LEN;

    // ---- load Q fragments into registers (scaled by 1/8, hi/lo split) ----
    uint32_t qh[4][4], ql[4][4];
    {
        const int rlo = r0 + w * 16 + (lane >> 2);
        const float* q0 = qb + (size_t)rlo * QKV_LD;
        const float* q1 = qb + (size_t)(rlo + 8) * QKV_LD;
#pragma unroll
        for (int ks = 0; ks < 4; ks++) {
            const int c = ks * 16 + (lane & 3) * 2;
            float2 x0 = *(const float2*)&q0[c];
            float2 x1 = *(const float2*)&q1[c];
            float2 x2 = *(const float2*)&q0[c + 8];
            float2 x3 = *(const float2*)&q1[c + 8];
            split_pack2(x0.x * 0.125f, x0.y * 0.125f, qh[ks][0], ql[ks][0]);
            split_pack2(x1.x * 0.125f, x1.y * 0.125f, qh[ks][1], ql[ks][1]);
            split_pack2(x2.x * 0.125f, x2.y * 0.125f, qh[ks][2], ql[ks][2]);
            split_pack2(x3.x * 0.125f, x3.y * 0.125f, qh[ks][3], ql[ks][3]);
        }
    }

    float m_i[2] = {-1e30f, -1e30f};
    float l_i[2] = {0.f, 0.f};
    float o_acc[8][4];
#pragma unroll
    for (int dt = 0; dt < 8; dt++)
#pragma unroll
        for (int r = 0; r < 4; r++) o_acc[dt][r] = 0.f;

    const int q0g = r0 + w * 16 + (lane >> 2);
    const int ntiles = (r0 + 128) >> 6;

    for (int t = 0; t < ntiles; t++) {
        const int k0 = t << 6;
        __syncthreads();
        // ---- load K,V tile: 64 keys x 64 dims ----
#pragma unroll
        for (int i = 0; i < 4; i++) {
            const int f   = tid + i * 256;          // 1024 float4s
            const int key = f >> 4;
            const int d4  = (f & 15) * 4;
            float4 kv = *(const float4*)&kb[(size_t)(k0 + key) * QKV_LD + d4];
            __nv_bfloat16 h0, l0, h1, l1, h2, l2, h3, l3;
            split2(kv.x, h0, l0); split2(kv.y, h1, l1);
            split2(kv.z, h2, l2); split2(kv.w, h3, l3);
            __nv_bfloat162 p01 = __nv_bfloat162(h0, h1), p23 = __nv_bfloat162(h2, h3);
            *(uint32_t*)&sKhi[key][d4]     = *(uint32_t*)&p01;
            *(uint32_t*)&sKhi[key][d4 + 2] = *(uint32_t*)&p23;
            __nv_bfloat162 q01 = __nv_bfloat162(l0, l1), q23 = __nv_bfloat162(l2, l3);
            *(uint32_t*)&sKlo[key][d4]     = *(uint32_t*)&q01;
            *(uint32_t*)&sKlo[key][d4 + 2] = *(uint32_t*)&q23;

            float4 vv = *(const float4*)&vb[(size_t)(k0 + key) * QKV_LD + d4];
            split2(vv.x, h0, l0); split2(vv.y, h1, l1);
            split2(vv.z, h2, l2); split2(vv.w, h3, l3);
            sVhi[d4 + 0][key] = h0;  sVlo[d4 + 0][key] = l0;
            sVhi[d4 + 1][key] = h1;  sVlo[d4 + 1][key] = l1;
            sVhi[d4 + 2][key] = h2;  sVlo[d4 + 2][key] = l2;
            sVhi[d4 + 3][key] = h3;  sVlo[d4 + 3][key] = l3;
        }
        if (tid < 64) sMask[tid] = mb[k0 + tid];
        __syncthreads();

        // ---- scores: S[16][64] per warp ----
        float s[8][4];
#pragma unroll
        for (int nt = 0; nt < 8; nt++)
#pragma unroll
            for (int r = 0; r < 4; r++) s[nt][r] = 0.f;

#pragma unroll
        for (int ks = 0; ks < 4; ks++) {
#pragma unroll
            for (int nt = 0; nt < 8; nt++) {
                const int key = nt * 8 + (lane >> 2);
                const int c   = ks * 16 + (lane & 3) * 2;
                uint32_t bfr[2], bfl[2];
                bfr[0] = *(const uint32_t*)&sKhi[key][c];
                bfr[1] = *(const uint32_t*)&sKhi[key][c + 8];
                bfl[0] = *(const uint32_t*)&sKlo[key][c];
                bfl[1] = *(const uint32_t*)&sKlo[key][c + 8];
                mma_bf16(s[nt], qh[ks], bfr);
                mma_bf16(s[nt], qh[ks], bfl);
                mma_bf16(s[nt], ql[ks], bfr);
            }
        }

        // ---- mask + online softmax (2 rows per thread) ----
#pragma unroll
        for (int row = 0; row < 2; row++) {
            const int qg = q0g + row * 8;
            float mx = -1e30f;
#pragma unroll
            for (int nt = 0; nt < 8; nt++)
#pragma unroll
                for (int c = 0; c < 2; c++) {
                    const int idx = row * 2 + c;
                    const int kl  = nt * 8 + (lane & 3) * 2 + c;
                    const bool ok = (sMask[kl] != 0u) && (k0 + kl <= qg);
                    s[nt][idx] = ok ? s[nt][idx] : -1e9f;
                    mx = fmaxf(mx, s[nt][idx]);
                }
            mx = fmaxf(mx, __shfl_xor_sync(0xffffffffu, mx, 1));
            mx = fmaxf(mx, __shfl_xor_sync(0xffffffffu, mx, 2));
            const float mnew = fmaxf(m_i[row], mx);
            const float corr = __expf(m_i[row] - mnew);
            float sum = 0.f;
#pragma unroll
            for (int nt = 0; nt < 8; nt++)
#pragma unroll
                for (int c = 0; c < 2; c++) {
                    const int idx = row * 2 + c;
                    const float p = __expf(s[nt][idx] - mnew);
                    s[nt][idx] = p;
                    sum += p;
                }
            sum += __shfl_xor_sync(0xffffffffu, sum, 1);
            sum += __shfl_xor_sync(0xffffffffu, sum, 2);
            l_i[row] = l_i[row] * corr + sum;
            m_i[row] = mnew;
#pragma unroll
            for (int dt = 0; dt < 8; dt++) {
                o_acc[dt][row * 2 + 0] *= corr;
                o_acc[dt][row * 2 + 1] *= corr;
            }
        }

        // ---- PV: pack P as A-frags (hi/lo), multiply with V^T ----
#pragma unroll
        for (int ks2 = 0; ks2 < 4; ks2++) {
            uint32_t pah[4], pal[4];
            split_pack2(s[ks2*2][0],   s[ks2*2][1],   pah[0], pal[0]);
            split_pack2(s[ks2*2][2],   s[ks2*2][3],   pah[1], pal[1]);
            split_pack2(s[ks2*2+1][0], s[ks2*2+1][1], pah[2], pal[2]);
            split_pack2(s[ks2*2+1][2], s[ks2*2+1][3], pah[3], pal[3]);
#pragma unroll
            for (int dt = 0; dt < 8; dt++) {
                const int d  = dt * 8 + (lane >> 2);
                const int kk = ks2 * 16 + (lane & 3) * 2;
                uint32_t bfr[2], bfl[2];
                bfr[0] = *(const uint32_t*)&sVhi[d][kk];
                bfr[1] = *(const uint32_t*)&sVhi[d][kk + 8];
                bfl[0] = *(const uint32_t*)&sVlo[d][kk];
                bfl[1] = *(const uint32_t*)&sVlo[d][kk + 8];
                mma_bf16(o_acc[dt], pah, bfr);
                mma_bf16(o_acc[dt], pah, bfl);
                mma_bf16(o_acc[dt], pal, bfr);
            }
        }
    }

    // ---- epilogue ----
    const float inv0 = 1.f / l_i[0];
    const float inv1 = 1.f / l_i[1];
    float* ob = g_ctx + ((size_t)b * S_LEN) * DMODEL + h * HDIM;
#pragma unroll
    for (int dt = 0; dt < 8; dt++) {
        const int col = dt * 8 + (lane & 3) * 2;
        float2 o0, o1;
        o0.x = o_acc[dt][0] * inv0;  o0.y = o_acc[dt][1] * inv0;
        o1.x = o_acc[dt][2] * inv1;  o1.y = o_acc[dt][3] * inv1;
        *(float2*)&ob[(size_t)q0g * DMODEL + col]       = o0;
        *(float2*)&ob[(size_t)(q0g + 8) * DMODEL + col] = o1;
    }
}

// ---------------------------------------------------------------------------
extern "C" void kernel_launch(void* const* d_in, const int* in_sizes, int n_in,
                              void* d_out, int out_size)
{
    const float*        tokens = (const float*)d_in[0];
    const unsigned int* mask   = (const unsigned int*)d_in[1];
    const int*          seqc   = (const int*)d_in[2];
    const float*        W_qkv  = (const float*)d_in[3];
    const float*        b_qkv  = (const float*)d_in[4];
    const float*        Wq     = (const float*)d_in[5];
    const float*        bq     = (const float*)d_in[6];
    const float*        Wk     = (const float*)d_in[7];
    const float*        bk     = (const float*)d_in[8];
    const float*        Wv     = (const float*)d_in[9];
    const float*        bv     = (const float*)d_in[10];
    const float*        W_out  = (const float*)d_in[11];
    const float*        b_out  = (const float*)d_in[12];
    float*              out    = (float*)d_out;

    float* qkv = nullptr;
    float* ctx = nullptr;
    cudaGetSymbolAddress((void**)&qkv, g_qkv);
    cudaGetSymbolAddress((void**)&ctx, g_ctx);

    const int M = BATCH * S_LEN;   // 4096

    dim3 g1(QKV_LD / 128, M / 128);
    gemm_bf16x3_kernel<<<g1, 256>>>(tokens, W_qkv, b_qkv, qkv, M, QKV_LD, DMODEL);

    ns_kernel<<<48, 256>>>(tokens, seqc, Wq, bq, Wk, bk, Wv, bv);

    dim3 g2(S_LEN / 128, BATCH * NHEADS);
    attn_tc_kernel<<<g2, 256>>>(mask);

    dim3 g3(DMODEL / 128, M / 128);
    gemm_bf16x3_kernel<<<g3, 256>>>(ctx, W_out, b_out, out, M, DMODEL, DMODEL);
}

// round 5
// speedup vs baseline: 2.1550x; 1.1301x over previous
#include <cuda_runtime.h>
#include <cuda_bf16.h>
#include <cstdint>

#define S_LEN   2048
#define DMODEL  1024
#define BATCH   2
#define NHEADS  16
#define HDIM    64
#define QKV_LD  3072
#define NKTILES (S_LEN / 64)    // 32 key tiles per (b,h)

__device__ float g_qkv[(size_t)BATCH * S_LEN * QKV_LD];
__device__ float g_ctx[(size_t)BATCH * S_LEN * DMODEL];
// Fragment-major bf16 hi/lo K and V^T: [bh][tile][group(32)][lane(32)] uint4
__device__ uint4 g_kfrag[(size_t)BATCH * NHEADS * NKTILES * 1024];
__device__ uint4 g_vfrag[(size_t)BATCH * NHEADS * NKTILES * 1024];

// ---------------------------------------------------------------------------
__device__ __forceinline__ void mma_bf16(float* d, const uint32_t* a, const uint32_t* b) {
    asm volatile(
        "mma.sync.aligned.m16n8k16.row.col.f32.bf16.bf16.f32 "
        "{%0,%1,%2,%3}, {%4,%5,%6,%7}, {%8,%9}, {%0,%1,%2,%3};\n"
        : "+f"(d[0]), "+f"(d[1]), "+f"(d[2]), "+f"(d[3])
        : "r"(a[0]), "r"(a[1]), "r"(a[2]), "r"(a[3]), "r"(b[0]), "r"(b[1]));
}

__device__ __forceinline__ void split2(float x, __nv_bfloat16& hi, __nv_bfloat16& lo) {
    hi = __float2bfloat16(x);
    lo = __float2bfloat16(x - __bfloat162float(hi));
}

__device__ __forceinline__ void split_pack2(float x, float y, uint32_t& hi, uint32_t& lo) {
    __nv_bfloat16 xh, xl, yh, yl;
    split2(x, xh, xl); split2(y, yh, yl);
    __nv_bfloat162 h2 = __nv_bfloat162(xh, yh);
    __nv_bfloat162 l2 = __nv_bfloat162(xl, yl);
    hi = *(uint32_t*)&h2;  lo = *(uint32_t*)&l2;
}

__device__ __forceinline__ void cp_async16(void* smem_ptr, const void* gptr) {
    uint32_t sa = (uint32_t)__cvta_generic_to_shared(smem_ptr);
    asm volatile("cp.async.cg.shared.global [%0], [%1], 16;\n" :: "r"(sa), "l"(gptr));
}
__device__ __forceinline__ void cp_commit() {
    asm volatile("cp.async.commit_group;\n");
}
template <int N>
__device__ __forceinline__ void cp_wait() {
    asm volatile("cp.async.wait_group %0;\n" :: "n"(N));
}

// ---------------------------------------------------------------------------
// bf16x3 compensated tensor-core GEMM (unchanged from R3/R4)
// ---------------------------------------------------------------------------
__global__ void __launch_bounds__(256) gemm_bf16x3_kernel(
    const float* __restrict__ A, const float* __restrict__ B,
    const float* __restrict__ bias, float* __restrict__ C,
    int M, int N, int K)
{
    __shared__ __nv_bfloat16 sAhi[128][40];
    __shared__ __nv_bfloat16 sAlo[128][40];
    __shared__ __nv_bfloat16 sBhi[32][136];
    __shared__ __nv_bfloat16 sBlo[32][136];

    const int tid    = threadIdx.x;
    const int lane   = tid & 31;
    const int wid    = tid >> 5;
    const int bm     = blockIdx.y * 128;
    const int bn     = blockIdx.x * 128;
    const int warp_m = (wid >> 2) * 64;
    const int warp_n = (wid & 3) * 32;

    float acc[4][4][4];
#pragma unroll
    for (int mi = 0; mi < 4; mi++)
#pragma unroll
        for (int ni = 0; ni < 4; ni++)
#pragma unroll
            for (int r = 0; r < 4; r++) acc[mi][ni][r] = 0.f;

    float4 av[4], bv[4];
#pragma unroll
    for (int i = 0; i < 4; i++) {
        const int f = tid + i * 256;
        av[i] = *(const float4*)&A[(size_t)(bm + (f >> 3)) * K + (f & 7) * 4];
        bv[i] = *(const float4*)&B[(size_t)(f >> 5) * N + bn + (f & 31) * 4];
    }

    for (int k0 = 0; k0 < K; k0 += 32) {
        __syncthreads();
#pragma unroll
        for (int i = 0; i < 4; i++) {
            const int f    = tid + i * 256;
            const int arow = f >> 3, acol = (f & 7) * 4;
            const int krow = f >> 5, ncol = (f & 31) * 4;
            __nv_bfloat16 h0, l0, h1, l1, h2, l2, h3, l3;
            split2(av[i].x, h0, l0); split2(av[i].y, h1, l1);
            split2(av[i].z, h2, l2); split2(av[i].w, h3, l3);
            sAhi[arow][acol+0] = h0; sAhi[arow][acol+1] = h1;
            sAhi[arow][acol+2] = h2; sAhi[arow][acol+3] = h3;
            sAlo[arow][acol+0] = l0; sAlo[arow][acol+1] = l1;
            sAlo[arow][acol+2] = l2; sAlo[arow][acol+3] = l3;
            split2(bv[i].x, h0, l0); split2(bv[i].y, h1, l1);
            split2(bv[i].z, h2, l2); split2(bv[i].w, h3, l3);
            sBhi[krow][ncol+0] = h0; sBhi[krow][ncol+1] = h1;
            sBhi[krow][ncol+2] = h2; sBhi[krow][ncol+3] = h3;
            sBlo[krow][ncol+0] = l0; sBlo[krow][ncol+1] = l1;
            sBlo[krow][ncol+2] = l2; sBlo[krow][ncol+3] = l3;
        }
        __syncthreads();

        if (k0 + 32 < K) {
            const int kn = k0 + 32;
#pragma unroll
            for (int i = 0; i < 4; i++) {
                const int f = tid + i * 256;
                av[i] = *(const float4*)&A[(size_t)(bm + (f >> 3)) * K + kn + (f & 7) * 4];
                bv[i] = *(const float4*)&B[(size_t)(kn + (f >> 5)) * N + bn + (f & 31) * 4];
            }
        }

#pragma unroll
        for (int ks = 0; ks < 2; ks++) {
            const int kb = ks * 16;
            uint32_t ah[4][4], al[4][4], bh[4][2], bl[4][2];
#pragma unroll
            for (int mi = 0; mi < 4; mi++) {
                const int m = warp_m + mi * 16 + (lane >> 2);
                const int c = kb + (lane & 3) * 2;
                ah[mi][0] = *(const uint32_t*)&sAhi[m][c];
                ah[mi][1] = *(const uint32_t*)&sAhi[m + 8][c];
                ah[mi][2] = *(const uint32_t*)&sAhi[m][c + 8];
                ah[mi][3] = *(const uint32_t*)&sAhi[m + 8][c + 8];
                al[mi][0] = *(const uint32_t*)&sAlo[m][c];
                al[mi][1] = *(const uint32_t*)&sAlo[m + 8][c];
                al[mi][2] = *(const uint32_t*)&sAlo[m][c + 8];
                al[mi][3] = *(const uint32_t*)&sAlo[m + 8][c + 8];
            }
#pragma unroll
            for (int ni = 0; ni < 4; ni++) {
                const int n  = warp_n + ni * 8 + (lane >> 2);
                const int kk = kb + (lane & 3) * 2;
                uint32_t u0, u1;
                u0 = *(const unsigned short*)&sBhi[kk][n];
                u1 = *(const unsigned short*)&sBhi[kk + 1][n];
                bh[ni][0] = u0 | (u1 << 16);
                u0 = *(const unsigned short*)&sBhi[kk + 8][n];
                u1 = *(const unsigned short*)&sBhi[kk + 9][n];
                bh[ni][1] = u0 | (u1 << 16);
                u0 = *(const unsigned short*)&sBlo[kk][n];
                u1 = *(const unsigned short*)&sBlo[kk + 1][n];
                bl[ni][0] = u0 | (u1 << 16);
                u0 = *(const unsigned short*)&sBlo[kk + 8][n];
                u1 = *(const unsigned short*)&sBlo[kk + 9][n];
                bl[ni][1] = u0 | (u1 << 16);
            }
#pragma unroll
            for (int mi = 0; mi < 4; mi++)
#pragma unroll
                for (int ni = 0; ni < 4; ni++) {
                    mma_bf16(acc[mi][ni], ah[mi], bh[ni]);
                    mma_bf16(acc[mi][ni], ah[mi], bl[ni]);
                    mma_bf16(acc[mi][ni], al[mi], bh[ni]);
                }
        }
    }

#pragma unroll
    for (int mi = 0; mi < 4; mi++) {
        const int row = bm + warp_m + mi * 16 + (lane >> 2);
#pragma unroll
        for (int ni = 0; ni < 4; ni++) {
            const int col = bn + warp_n + ni * 8 + (lane & 3) * 2;
            const float2 bb = *(const float2*)&bias[col];
            float2 o0, o1;
            o0.x = acc[mi][ni][0] + bb.x;  o0.y = acc[mi][ni][1] + bb.y;
            o1.x = acc[mi][ni][2] + bb.x;  o1.y = acc[mi][ni][3] + bb.y;
            *(float2*)&C[(size_t)row * N + col]       = o0;
            *(float2*)&C[(size_t)(row + 8) * N + col] = o1;
        }
    }
}

// ---------------------------------------------------------------------------
// ns overwrite (unchanged)
// ---------------------------------------------------------------------------
__global__ void __launch_bounds__(256) ns_kernel(
    const float* __restrict__ tokens, const int* __restrict__ seqc,
    const float* __restrict__ Wq, const float* __restrict__ bq,
    const float* __restrict__ Wk, const float* __restrict__ bk,
    const float* __restrict__ Wv, const float* __restrict__ bv)
{
    __shared__ float st[DMODEL];
    const int bxid = blockIdx.x;
    const int mat = bxid >> 4;
    const int b   = (bxid >> 3) & 1;
    const int n   = bxid & 7;

    const int pos = *seqc;
    const int row = pos + n;
    if (pos < 0 || row < 0 || row >= S_LEN) return;

    const float* W; const float* bb;
    if (mat == 0)      { W = Wq; bb = bq; }
    else if (mat == 1) { W = Wk; bb = bk; }
    else               { W = Wv; bb = bv; }
    W  += (size_t)n * DMODEL * DMODEL;
    bb += n * DMODEL;

    const float* trow = tokens + ((size_t)b * S_LEN + row) * DMODEL;
    const int tid = threadIdx.x;
    *(float4*)&st[tid * 4] = *(const float4*)&trow[tid * 4];
    __syncthreads();

    float acc[4];
#pragma unroll
    for (int j = 0; j < 4; j++) acc[j] = bb[tid + 256 * j];

    for (int d = 0; d < DMODEL; d++) {
        const float td = st[d];
        const float* wr = W + (size_t)d * DMODEL;
#pragma unroll
        for (int j = 0; j < 4; j++) acc[j] += td * wr[tid + 256 * j];
    }

    float* out = g_qkv + ((size_t)b * S_LEN + row) * QKV_LD + mat * DMODEL;
#pragma unroll
    for (int j = 0; j < 4; j++) out[tid + 256 * j] = acc[j];
}

// ---------------------------------------------------------------------------
// Presplit: K and V^T of every (b,h,64-key tile) -> fragment-major bf16 hi/lo.
// Fragment word layout (uint4 per [group][lane]):
//   K:  group g = nt*4+ks; key = nt*8+(lane>>2); c = ks*16+(lane&3)*2
//       {hi(c,c+1), hi(c+8,c+9), lo(c,c+1), lo(c+8,c+9)}
//   V^T: group g = dt*4+ks2; d = dt*8+(lane>>2); kk = ks2*16+(lane&3)*2
//       {hi(V[kk][d],V[kk+1][d]), hi(kk+8,kk+9), lo(...), lo(...)}
// ---------------------------------------------------------------------------
__global__ void __launch_bounds__(256) presplit_kernel()
{
    __shared__ float stage[64][68];
    const int tile = blockIdx.x;
    const int bh   = blockIdx.y;
    const int b    = bh >> 4;
    const int h    = bh & 15;
    const int tid  = threadIdx.x;

    const float* kb = g_qkv + ((size_t)b * S_LEN + tile * 64) * QKV_LD + DMODEL + h * HDIM;
    const float* vb = kb + DMODEL;
    const size_t obase = ((size_t)bh * NKTILES + tile) << 10;

    // ---- K ----
#pragma unroll
    for (int i = 0; i < 4; i++) {
        const int f = tid + i * 256;
        *(float4*)&stage[f >> 4][(f & 15) * 4] =
            *(const float4*)&kb[(size_t)(f >> 4) * QKV_LD + (f & 15) * 4];
    }
    __syncthreads();
#pragma unroll
    for (int i = 0; i < 4; i++) {
        const int s = tid + i * 256;
        const int g = s >> 5, l = s & 31;
        const int key = (g >> 2) * 8 + (l >> 2);
        const int c   = (g & 3) * 16 + (l & 3) * 2;
        __nv_bfloat16 h0,l0,h1,l1,h2,l2,h3,l3;
        split2(stage[key][c],     h0, l0);
        split2(stage[key][c + 1], h1, l1);
        split2(stage[key][c + 8], h2, l2);
        split2(stage[key][c + 9], h3, l3);
        __nv_bfloat162 w0(h0,h1), w1(h2,h3), w2(l0,l1), w3(l2,l3);
        g_kfrag[obase + s] = make_uint4(*(uint32_t*)&w0, *(uint32_t*)&w1,
                                        *(uint32_t*)&w2, *(uint32_t*)&w3);
    }
    __syncthreads();

    // ---- V (transposed fragments) ----
#pragma unroll
    for (int i = 0; i < 4; i++) {
        const int f = tid + i * 256;
        *(float4*)&stage[f >> 4][(f & 15) * 4] =
            *(const float4*)&vb[(size_t)(f >> 4) * QKV_LD + (f & 15) * 4];
    }
    __syncthreads();
#pragma unroll
    for (int i = 0; i < 4; i++) {
        const int s = tid + i * 256;
        const int g = s >> 5, l = s & 31;
        const int d  = (g >> 2) * 8 + (l >> 2);
        const int kk = (g & 3) * 16 + (l & 3) * 2;
        __nv_bfloat16 h0,l0,h1,l1,h2,l2,h3,l3;
        split2(stage[kk][d],     h0, l0);
        split2(stage[kk + 1][d], h1, l1);
        split2(stage[kk + 8][d], h2, l2);
        split2(stage[kk + 9][d], h3, l3);
        __nv_bfloat162 w0(h0,h1), w1(h2,h3), w2(l0,l1), w3(l2,l3);
        g_vfrag[obase + s] = make_uint4(*(uint32_t*)&w0, *(uint32_t*)&w1,
                                        *(uint32_t*)&w2, *(uint32_t*)&w3);
    }
}

// ---------------------------------------------------------------------------
// Tensor-core flash attention on presplit fragments.
// 128 q rows/block, 8 warps; 64-key tiles; cp.async double-buffered smem.
// ---------------------------------------------------------------------------
__global__ void __launch_bounds__(256) attn_tc_kernel(
    const unsigned int* __restrict__ mask)
{
    extern __shared__ uint4 dyn[];
    uint4*    sK    = dyn;                 // [2][1024]
    uint4*    sV    = dyn + 2048;          // [2][1024]
    uint32_t* sMask = (uint32_t*)(dyn + 4096);  // [2][64]

    const int tid  = threadIdx.x;
    const int w    = tid >> 5;
    const int lane = tid & 31;
    const int bxr  = (S_LEN / 128 - 1) - blockIdx.x;   // heavy blocks first
    const int bh   = blockIdx.y;
    const int b    = bh >> 4;
    const int h    = bh & 15;
    const int r0   = bxr * 128;

    const float* qb = g_qkv + ((size_t)b * S_LEN) * QKV_LD + h * HDIM;
    const unsigned int* mb = mask + b * S_LEN;
    const uint4* kfb = g_kfrag + ((size_t)bh * NKTILES << 10);
    const uint4* vfb = g_vfrag + ((size_t)bh * NKTILES << 10);

    const int ntiles = (r0 + 128) >> 6;

    // ---- Q fragments (scaled by 1/8, hi/lo) ----
    uint32_t qh[4][4], ql[4][4];
    {
        const int rlo = r0 + w * 16 + (lane >> 2);
        const float* q0 = qb + (size_t)rlo * QKV_LD;
        const float* q1 = qb + (size_t)(rlo + 8) * QKV_LD;
#pragma unroll
        for (int ks = 0; ks < 4; ks++) {
            const int c = ks * 16 + (lane & 3) * 2;
            float2 x0 = *(const float2*)&q0[c];
            float2 x1 = *(const float2*)&q1[c];
            float2 x2 = *(const float2*)&q0[c + 8];
            float2 x3 = *(const float2*)&q1[c + 8];
            split_pack2(x0.x * 0.125f, x0.y * 0.125f, qh[ks][0], ql[ks][0]);
            split_pack2(x1.x * 0.125f, x1.y * 0.125f, qh[ks][1], ql[ks][1]);
            split_pack2(x2.x * 0.125f, x2.y * 0.125f, qh[ks][2], ql[ks][2]);
            split_pack2(x3.x * 0.125f, x3.y * 0.125f, qh[ks][3], ql[ks][3]);
        }
    }

    float m_i[2] = {-1e30f, -1e30f};
    float l_i[2] = {0.f, 0.f};
    float o_acc[8][4];
#pragma unroll
    for (int dt = 0; dt < 8; dt++)
#pragma unroll
        for (int r = 0; r < 4; r++) o_acc[dt][r] = 0.f;

    const int q0g = r0 + w * 16 + (lane >> 2);

    // prologue: stage tile 0
    {
        const uint4* srcK = kfb;
        const uint4* srcV = vfb;
#pragma unroll
        for (int i = 0; i < 4; i++) {
            const int idx = tid + i * 256;
            cp_async16(&sK[idx], srcK + idx);
            cp_async16(&sV[idx], srcV + idx);
        }
        if (tid < 16) cp_async16(&sMask[tid * 4], mb + tid * 4);
        cp_commit();
    }

    for (int t = 0; t < ntiles; t++) {
        const int buf = t & 1;
        if (t + 1 < ntiles) {
            const int nb = (t + 1) & 1;
            const uint4* srcK = kfb + ((size_t)(t + 1) << 10);
            const uint4* srcV = vfb + ((size_t)(t + 1) << 10);
#pragma unroll
            for (int i = 0; i < 4; i++) {
                const int idx = tid + i * 256;
                cp_async16(&sK[nb * 1024 + idx], srcK + idx);
                cp_async16(&sV[nb * 1024 + idx], srcV + idx);
            }
            if (tid < 16) cp_async16(&sMask[nb * 64 + tid * 4], mb + (t + 1) * 64 + tid * 4);
            cp_commit();
            cp_wait<1>();
        } else {
            cp_wait<0>();
        }
        __syncthreads();

        const int k0 = t << 6;
        const uint4* bK = sK + buf * 1024;
        const uint4* bV = sV + buf * 1024;
        const uint32_t* bM = sMask + buf * 64;

        // ---- scores: S[16][64] per warp ----
        float s[8][4];
#pragma unroll
        for (int nt = 0; nt < 8; nt++)
#pragma unroll
            for (int r = 0; r < 4; r++) s[nt][r] = 0.f;

#pragma unroll
        for (int ks = 0; ks < 4; ks++) {
#pragma unroll
            for (int nt = 0; nt < 8; nt++) {
                const uint4 v = bK[(nt * 4 + ks) * 32 + lane];
                uint32_t bfr[2] = {v.x, v.y};
                uint32_t bfl[2] = {v.z, v.w};
                mma_bf16(s[nt], qh[ks], bfr);
                mma_bf16(s[nt], qh[ks], bfl);
                mma_bf16(s[nt], ql[ks], bfr);
            }
        }

        // ---- mask + online softmax ----
#pragma unroll
        for (int row = 0; row < 2; row++) {
            const int qg = q0g + row * 8;
            float mx = -1e30f;
#pragma unroll
            for (int nt = 0; nt < 8; nt++)
#pragma unroll
                for (int c = 0; c < 2; c++) {
                    const int idx = row * 2 + c;
                    const int kl  = nt * 8 + (lane & 3) * 2 + c;
                    const bool ok = (bM[kl] != 0u) && (k0 + kl <= qg);
                    s[nt][idx] = ok ? s[nt][idx] : -1e9f;
                    mx = fmaxf(mx, s[nt][idx]);
                }
            mx = fmaxf(mx, __shfl_xor_sync(0xffffffffu, mx, 1));
            mx = fmaxf(mx, __shfl_xor_sync(0xffffffffu, mx, 2));
            const float mnew = fmaxf(m_i[row], mx);
            const float corr = __expf(m_i[row] - mnew);
            float sum = 0.f;
#pragma unroll
            for (int nt = 0; nt < 8; nt++)
#pragma unroll
                for (int c = 0; c < 2; c++) {
                    const int idx = row * 2 + c;
                    const float p = __expf(s[nt][idx] - mnew);
                    s[nt][idx] = p;
                    sum += p;
                }
            sum += __shfl_xor_sync(0xffffffffu, sum, 1);
            sum += __shfl_xor_sync(0xffffffffu, sum, 2);
            l_i[row] = l_i[row] * corr + sum;
            m_i[row] = mnew;
#pragma unroll
            for (int dt = 0; dt < 8; dt++) {
                o_acc[dt][row * 2 + 0] *= corr;
                o_acc[dt][row * 2 + 1] *= corr;
            }
        }

        // ---- PV ----
#pragma unroll
        for (int ks2 = 0; ks2 < 4; ks2++) {
            uint32_t pah[4], pal[4];
            split_pack2(s[ks2*2][0],   s[ks2*2][1],   pah[0], pal[0]);
            split_pack2(s[ks2*2][2],   s[ks2*2][3],   pah[1], pal[1]);
            split_pack2(s[ks2*2+1][0], s[ks2*2+1][1], pah[2], pal[2]);
            split_pack2(s[ks2*2+1][2], s[ks2*2+1][3], pah[3], pal[3]);
#pragma unroll
            for (int dt = 0; dt < 8; dt++) {
                const uint4 v = bV[(dt * 4 + ks2) * 32 + lane];
                uint32_t bfr[2] = {v.x, v.y};
                uint32_t bfl[2] = {v.z, v.w};
                mma_bf16(o_acc[dt], pah, bfr);
                mma_bf16(o_acc[dt], pah, bfl);
                mma_bf16(o_acc[dt], pal, bfr);
            }
        }
        __syncthreads();
    }

    // ---- epilogue ----
    const float inv0 = 1.f / l_i[0];
    const float inv1 = 1.f / l_i[1];
    float* ob = g_ctx + ((size_t)b * S_LEN) * DMODEL + h * HDIM;
#pragma unroll
    for (int dt = 0; dt < 8; dt++) {
        const int col = dt * 8 + (lane & 3) * 2;
        float2 o0, o1;
        o0.x = o_acc[dt][0] * inv0;  o0.y = o_acc[dt][1] * inv0;
        o1.x = o_acc[dt][2] * inv1;  o1.y = o_acc[dt][3] * inv1;
        *(float2*)&ob[(size_t)q0g * DMODEL + col]       = o0;
        *(float2*)&ob[(size_t)(q0g + 8) * DMODEL + col] = o1;
    }
}

// ---------------------------------------------------------------------------
extern "C" void kernel_launch(void* const* d_in, const int* in_sizes, int n_in,
                              void* d_out, int out_size)
{
    const float*        tokens = (const float*)d_in[0];
    const unsigned int* mask   = (const unsigned int*)d_in[1];
    const int*          seqc   = (const int*)d_in[2];
    const float*        W_qkv  = (const float*)d_in[3];
    const float*        b_qkv  = (const float*)d_in[4];
    const float*        Wq     = (const float*)d_in[5];
    const float*        bq     = (const float*)d_in[6];
    const float*        Wk     = (const float*)d_in[7];
    const float*        bk     = (const float*)d_in[8];
    const float*        Wv     = (const float*)d_in[9];
    const float*        bv     = (const float*)d_in[10];
    const float*        W_out  = (const float*)d_in[11];
    const float*        b_out  = (const float*)d_in[12];
    float*              out    = (float*)d_out;

    float* qkv = nullptr;
    float* ctx = nullptr;
    cudaGetSymbolAddress((void**)&qkv, g_qkv);
    cudaGetSymbolAddress((void**)&ctx, g_ctx);

    static bool attr_set = false;
    if (!attr_set) {
        cudaFuncSetAttribute(attn_tc_kernel,
                             cudaFuncAttributeMaxDynamicSharedMemorySize, 66048);
        attr_set = true;
    }

    const int M = BATCH * S_LEN;   // 4096

    dim3 g1(QKV_LD / 128, M / 128);
    gemm_bf16x3_kernel<<<g1, 256>>>(tokens, W_qkv, b_qkv, qkv, M, QKV_LD, DMODEL);

    ns_kernel<<<48, 256>>>(tokens, seqc, Wq, bq, Wk, bk, Wv, bv);

    dim3 gp(NKTILES, BATCH * NHEADS);
    presplit_kernel<<<gp, 256>>>();

    dim3 g2(S_LEN / 128, BATCH * NHEADS);
    attn_tc_kernel<<<g2, 256, 66048>>>(mask);

    dim3 g3(DMODEL / 128, M / 128);
    gemm_bf16x3_kernel<<<g3, 256>>>(ctx, W_out, b_out, out, M, DMODEL, DMODEL);
}